// round 12
// baseline (speedup 1.0000x reference)
#include <cuda_runtime.h>
#include <cuda_bf16.h>

#define NCTA 128
#define NTHR 512
#define TSTEPS 512

typedef unsigned long long u64;
typedef unsigned int u32;

// ---------------- persistent device state ----------------
__device__ float g_hT[1024 * 64];                       // fp32 h, [col][row], for head only
__device__ __align__(16) uint4 g_Phi[7][8192];          // fragment-order A planes (bf16-hi)
__device__ __align__(16) uint4 g_Plo[7][8192];          // fragment-order A planes (bf16-lo)
// plane ids: 0=emb 1=s0 2=s1 3=s2 4=s3 5=s5 6=h
__device__ u64 g_Whi[5242880];                          // fragment-order B weights, bf16-hi
__device__ u64 g_Wlo[5242880];                          // bf16-lo
__device__ unsigned g_flags[NCTA];                      // per-CTA barrier flags (monotonic)

#define WOFF(i) (1048576u + (u32)(i) * 524288u)         // u64 offset of node-i weights

// ---------------- helpers ----------------
__device__ __forceinline__ float sigm(float x) { return 1.f / (1.f + expf(-x)); }
__device__ __forceinline__ float actf(int code, float x) {
    switch (code) {
        case 0:  return tanhf(x);
        case 1:  return fmaxf(x, 0.f);
        case 2:  return sigm(x);
        default: return x;
    }
}
__device__ __forceinline__ float ldcg_f(const float* p) {
    float v; asm volatile("ld.global.cg.f32 %0, [%1];" : "=f"(v) : "l"(p)); return v;
}
__device__ __forceinline__ uint4 ldcg_u4(const uint4* p) {
    uint4 v;
    asm volatile("ld.global.cg.v4.u32 {%0,%1,%2,%3}, [%4];"
                 : "=r"(v.x), "=r"(v.y), "=r"(v.z), "=r"(v.w) : "l"(p));
    return v;
}

__device__ __forceinline__ void mma_bf16(float* d, u32 a0, u32 a1, u32 a2, u32 a3,
                                         u32 b0, u32 b1) {
    asm("mma.sync.aligned.m16n8k16.row.col.f32.bf16.bf16.f32 "
        "{%0,%1,%2,%3},{%4,%5,%6,%7},{%8,%9},{%0,%1,%2,%3};"
        : "+f"(d[0]), "+f"(d[1]), "+f"(d[2]), "+f"(d[3])
        : "r"(a0), "r"(a1), "r"(a2), "r"(a3), "r"(b0), "r"(b1));
}

__device__ __forceinline__ u64 pack4(__nv_bfloat16 a, __nv_bfloat16 b,
                                     __nv_bfloat16 c, __nv_bfloat16 d) {
    return (u64)__bfloat16_as_ushort(a) | ((u64)__bfloat16_as_ushort(b) << 16)
         | ((u64)__bfloat16_as_ushort(c) << 32) | ((u64)__bfloat16_as_ushort(d) << 48);
}
__device__ __forceinline__ void packhl(float v0, float v1, float v2, float v3,
                                       u64& hi, u64& lo) {
    __nv_bfloat16 h0 = __float2bfloat16_rn(v0), h1 = __float2bfloat16_rn(v1),
                  h2 = __float2bfloat16_rn(v2), h3 = __float2bfloat16_rn(v3);
    __nv_bfloat16 l0 = __float2bfloat16_rn(v0 - __bfloat162float(h0)),
                  l1 = __float2bfloat16_rn(v1 - __bfloat162float(h1)),
                  l2 = __float2bfloat16_rn(v2 - __bfloat162float(h2)),
                  l3 = __float2bfloat16_rn(v3 - __bfloat162float(h3));
    hi = pack4(h0, h1, h2, h3);
    lo = pack4(l0, l1, l2, l3);
}

// Flag-array grid barrier (R4-proven): parallel per-CTA flag stores, 128 pollers.
// Mutable state is read via ld.cg (L2), so no L1-invalidate needed.
__device__ __forceinline__ void grid_sync(unsigned e) {
    __threadfence();
    __syncthreads();
    if (threadIdx.x == 0)
        *((volatile unsigned*)&g_flags[blockIdx.x]) = e;
    if (threadIdx.x < NCTA) {
        while (*((volatile unsigned*)&g_flags[threadIdx.x]) < e) { }
    }
    __syncthreads();
}

// Write this CTA's 8 state cols (scratch[col*65+row]) into an A plane, fragment-order.
__device__ __forceinline__ void swz_scr(const float* sc, u64* dh, u64* dl, int cta, int tt) {
    int mt = tt >> 5, lane = tt & 31, g = lane >> 2, c = lane & 3;
    int jA = 2 * c, mA = mt * 16 + g, mB = mA + 8;
    float v00 = sc[jA * 65 + mA], v01 = sc[(jA + 1) * 65 + mA];
    float v10 = sc[jA * 65 + mB], v11 = sc[(jA + 1) * 65 + mB];
    u64 hi, lo; packhl(v00, v01, v10, v11, hi, lo);
    int idx = ((((cta >> 1) * 4 + mt) * 32 + lane) << 1) + (cta & 1);
    dh[idx] = hi; dl[idx] = lo;
}

// Gather embedding rows directly into the fragment-order emb plane.
__device__ __forceinline__ void swz_emb(const float* __restrict__ emb, const int* stok,
                                        u64* dh, u64* dl, int cta, int j0, int tt) {
    int mt = tt >> 5, lane = tt & 31, g = lane >> 2, c = lane & 3;
    int jA = j0 + 2 * c, mA = mt * 16 + g, mB = mA + 8;
    size_t tA = (size_t)stok[mA] * 1024, tB = (size_t)stok[mB] * 1024;
    float v00 = __ldg(emb + tA + jA), v01 = __ldg(emb + tA + jA + 1);
    float v10 = __ldg(emb + tB + jA), v11 = __ldg(emb + tB + jA + 1);
    u64 hi, lo; packhl(v00, v01, v10, v11, hi, lo);
    int idx = ((((cta >> 1) * 4 + mt) * 32 + lane) << 1) + (cta & 1);
    dh[idx] = hi; dl[idx] = lo;
}

struct ND {
    const u64* wh; const u64* wl;   // fragment-order weights (node offset applied)
    int act;                        // 0 tanh 1 relu 2 sigmoid 3 id
    float sp;                       // per-thread gate base (pred state element)
    u64* szh; u64* szl;             // output plane (null = skip)
};

// One level: NN nodes sharing the same A operand. 16 warps = 4 mt x 2 nt x 2 kh;
// kh takes a blocked half of the K-tiles (plane-aligned for L0). Direct LDG of both
// operands, zero syncs in the K loop.
template<int NN>
__device__ __forceinline__ void gemm_level(
    const uint4* __restrict__ PhA, const uint4* __restrict__ PlA,
    const uint4* __restrict__ PhB, const uint4* __restrict__ PlB,
    int half_nkt, int nkt, ND* nd, float* outv,
    float* bufA, float* bufB, float* scratch, int cta)
{
    const int tid = threadIdx.x;
    const int lane = tid & 31, warp = tid >> 5;
    const int mt = warp & 3, nt = (warp >> 2) & 1, kh = warp >> 3;
    const int n8c = cta + (nt << 7);
    const u32 bbase = (u32)n8c * (u32)nkt * 32u + (u32)lane + (u32)(kh * half_nkt) * 32u;

    const uint4* Pa_h = (kh ? PhB : PhA) + mt * 32 + lane;
    const uint4* Pa_l = (kh ? PlB : PlA) + mt * 32 + lane;

    float acc[NN][4];
    #pragma unroll
    for (int n = 0; n < NN; n++)
        #pragma unroll
        for (int i = 0; i < 4; i++) acc[n][i] = 0.f;

    #pragma unroll 2
    for (int i = 0; i < half_nkt; i++) {
        uint4 ah = ldcg_u4(Pa_h + i * 128);
        uint4 al = ldcg_u4(Pa_l + i * 128);
        #pragma unroll
        for (int n = 0; n < NN; n++) {
            u64 bh = __ldg(nd[n].wh + bbase + (u32)i * 32u);
            u64 bl = __ldg(nd[n].wl + bbase + (u32)i * 32u);
            u32 bh0 = (u32)bh, bh1 = (u32)(bh >> 32);
            u32 bl0 = (u32)bl, bl1 = (u32)(bl >> 32);
            mma_bf16(acc[n], ah.x, ah.y, ah.z, ah.w, bh0, bh1);
            mma_bf16(acc[n], ah.x, ah.y, ah.z, ah.w, bl0, bl1);
            mma_bf16(acc[n], al.x, al.y, al.z, al.w, bh0, bh1);
        }
    }

    // per-node cross-kh reduction + epilogue
    const int c8 = tid & 7, row = tid >> 3;
    const int nl = nt * 8 + 2 * (lane & 3);
    const int m  = mt * 16 + (lane >> 2);
    float* mybuf = kh ? bufB : bufA;

    #pragma unroll
    for (int n = 0; n < NN; n++) {
        mybuf[nl * 68 + m]           = acc[n][0];
        mybuf[(nl + 1) * 68 + m]     = acc[n][1];
        mybuf[nl * 68 + m + 8]       = acc[n][2];
        mybuf[(nl + 1) * 68 + m + 8] = acc[n][3];
        __syncthreads();
        float cpre = bufA[c8 * 68 + row] + bufB[c8 * 68 + row];
        float hpre = bufA[(8 + c8) * 68 + row] + bufB[(8 + c8) * 68 + row];
        float cv = sigm(cpre);
        float hv = actf(nd[n].act, hpre);
        float sp = nd[n].sp;
        float val = sp + cv * (hv - sp);
        outv[n] = val;
        if (nd[n].szh) {
            scratch[c8 * 65 + row] = val;
            __syncthreads();
            if (tid < 128) swz_scr(scratch, nd[n].szh, nd[n].szl, cta, tid);
        }
        __syncthreads();
    }
}

// ---------------- the persistent kernel ----------------
__global__ __launch_bounds__(NTHR, 1) void darts_mma_kernel(
    const int* __restrict__ X, const float* __restrict__ hidden,
    const float* __restrict__ emb, const float* __restrict__ W0,
    const float* __restrict__ Ws, const float* __restrict__ Wout,
    const float* __restrict__ bout, float* __restrict__ out, int out_size)
{
    __shared__ float bufA[16 * 68], bufB[16 * 68];
    __shared__ float scratch[8 * 65];
    __shared__ int stok[64];

    const int cta = blockIdx.x;
    const int tid = threadIdx.x;
    const int j0 = cta * 8;
    const int c8 = tid & 7, row = tid >> 3;
    unsigned epoch = *((volatile unsigned*)&g_flags[cta]);   // equal across CTAs at entry

    // Phase 1: weights fp32 -> fragment-order bf16 hi/lo quads (every launch).
    for (u32 q = (u32)(cta * NTHR + tid); q < 5242880u; q += (u32)(NCTA * NTHR)) {
        const float* src; u32 rem, ktmask, n8sh;
        if (q < 1048576u) { src = W0; rem = q; ktmask = 127u; n8sh = 7u; }
        else {
            u32 r = q - 1048576u;
            src = Ws + (size_t)(r >> 19) * 2097152u;
            rem = r & 524287u; ktmask = 63u; n8sh = 6u;
        }
        u32 lane = rem & 31u, t2 = rem >> 5;
        u32 kt = t2 & ktmask, n8 = t2 >> n8sh;
        u32 g = lane >> 2, c = lane & 3;
        u32 k0 = kt * 16 + 2 * c;
        u32 n = n8 * 8 + g;
        float v0 = __ldg(src + (size_t)k0 * 2048 + n);
        float v1 = __ldg(src + (size_t)(k0 + 1) * 2048 + n);
        float v2 = __ldg(src + (size_t)(k0 + 8) * 2048 + n);
        float v3 = __ldg(src + (size_t)(k0 + 9) * 2048 + n);
        u64 hi, lo; packhl(v0, v1, v2, v3, hi, lo);
        g_Whi[q] = hi; g_Wlo[q] = lo;
    }

    // Phase 2: init h plane and emb plane for t=0.
    float hreg = __ldg(&hidden[row * 1024 + j0 + c8]);
    scratch[c8 * 65 + row] = hreg;
    if (tid < 64) stok[tid] = __ldg(&X[tid]);
    __syncthreads();
    if (tid < 128) swz_scr(scratch, (u64*)g_Phi[6], (u64*)g_Plo[6], cta, tid);
    else if (tid < 256) swz_emb(emb, stok, (u64*)g_Phi[0], (u64*)g_Plo[0], cta, j0, tid - 128);
    grid_sync(++epoch);

    float sv1, sv2, sv3, sv5;
    float o[3];
    ND nd[3];

    for (int t = 0; t < TSTEPS; t++) {
        // L0: s0 = gate([emb;h] @ W0), base h, tanh. K=2048: kh=0 emb plane, kh=1 h plane.
        nd[0] = { g_Whi, g_Wlo, 0, hreg, (u64*)g_Phi[1], (u64*)g_Plo[1] };
        gemm_level<1>(g_Phi[0], g_Plo[0], g_Phi[6], g_Plo[6], 64, 128,
                      nd, o, bufA, bufB, scratch, cta);
        float sv0 = o[0];
        grid_sync(++epoch);

        // L1: s1 = node0(s0), sigmoid
        nd[0] = { g_Whi + WOFF(0), g_Wlo + WOFF(0), 2, sv0, (u64*)g_Phi[2], (u64*)g_Plo[2] };
        gemm_level<1>(g_Phi[1], g_Plo[1], g_Phi[1] + 4096, g_Plo[1] + 4096, 32, 64,
                      nd, o, bufA, bufB, scratch, cta);
        sv1 = o[0];
        grid_sync(++epoch);

        // L2: s2=node1(s1) relu, s3=node2(s1) relu, s4=node3(s1) id — share A=s1
        nd[0] = { g_Whi + WOFF(1), g_Wlo + WOFF(1), 1, sv1, (u64*)g_Phi[3], (u64*)g_Plo[3] };
        nd[1] = { g_Whi + WOFF(2), g_Wlo + WOFF(2), 1, sv1, (u64*)g_Phi[4], (u64*)g_Plo[4] };
        nd[2] = { g_Whi + WOFF(3), g_Wlo + WOFF(3), 3, sv1, (u64*)0, (u64*)0 };
        gemm_level<3>(g_Phi[2], g_Plo[2], g_Phi[2] + 4096, g_Plo[2] + 4096, 32, 64,
                      nd, o, bufA, bufB, scratch, cta);
        sv2 = o[0]; sv3 = o[1];
        float sv4 = o[2];
        grid_sync(++epoch);

        // L3: s5 = node4(s2), tanh
        nd[0] = { g_Whi + WOFF(4), g_Wlo + WOFF(4), 0, sv2, (u64*)g_Phi[5], (u64*)g_Plo[5] };
        gemm_level<1>(g_Phi[3], g_Plo[3], g_Phi[3] + 4096, g_Plo[3] + 4096, 32, 64,
                      nd, o, bufA, bufB, scratch, cta);
        sv5 = o[0];
        grid_sync(++epoch);

        // L4a: s7 = node6(s3), tanh (A = s3 plane)
        nd[0] = { g_Whi + WOFF(6), g_Wlo + WOFF(6), 0, sv3, (u64*)0, (u64*)0 };
        gemm_level<1>(g_Phi[4], g_Plo[4], g_Phi[4] + 4096, g_Plo[4] + 4096, 32, 64,
                      nd, o, bufA, bufB, scratch, cta);
        float sv7 = o[0];

        // L4b: s6 = node5(s5) sigmoid, s8 = node7(s5) relu (A = s5 plane)
        nd[0] = { g_Whi + WOFF(5), g_Wlo + WOFF(5), 2, sv5, (u64*)0, (u64*)0 };
        nd[1] = { g_Whi + WOFF(7), g_Wlo + WOFF(7), 1, sv5, (u64*)0, (u64*)0 };
        gemm_level<2>(g_Phi[5], g_Plo[5], g_Phi[5] + 4096, g_Plo[5] + 4096, 32, 64,
                      nd, o, bufA, bufB, scratch, cta);
        float sv6 = o[0], sv8 = o[1];

        // combine: h = mean(s1..s8) in registers; write h plane + next emb plane
        hreg = 0.125f * (sv1 + sv2 + sv3 + sv4 + sv5 + sv6 + sv7 + sv8);
        scratch[c8 * 65 + row] = hreg;
        if (tid < 64 && t + 1 < TSTEPS) stok[tid] = __ldg(&X[(t + 1) * 64 + tid]);
        __syncthreads();
        if (tid < 128) swz_scr(scratch, (u64*)g_Phi[6], (u64*)g_Plo[6], cta, tid);
        else if (tid < 256 && t + 1 < TSTEPS)
            swz_emb(emb, stok, (u64*)g_Phi[0], (u64*)g_Plo[0], cta, j0, tid - 128);
        grid_sync(++epoch);
    }

    // publish final h for the head
    g_hT[(j0 + c8) * 64 + row] = hreg;
    grid_sync(++epoch);

    // head: a_hat = h @ W_out + b_out; probs = softmax over 4 (lane-aligned groups)
    if (cta == 0 && tid < 256) {
        int b = tid >> 2, oo = tid & 3;
        float acc = 0.f;
        for (int k = 0; k < 1024; k++)
            acc += ldcg_f(&g_hT[k * 64 + b]) * __ldg(&Wout[k * 4 + oo]);
        acc += __ldg(&bout[oo]);
        float mx = acc;
        mx = fmaxf(mx, __shfl_xor_sync(0xFFFFFFFFu, mx, 1));
        mx = fmaxf(mx, __shfl_xor_sync(0xFFFFFFFFu, mx, 2));
        float e = expf(acc - mx);
        float ssum = e;
        ssum += __shfl_xor_sync(0xFFFFFFFFu, ssum, 1);
        ssum += __shfl_xor_sync(0xFFFFFFFFu, ssum, 2);
        out[b * 4 + oo] = acc;
        if (out_size >= 512) out[256 + b * 4 + oo] = e / ssum;
    }
}

extern "C" void kernel_launch(void* const* d_in, const int* in_sizes, int n_in,
                              void* d_out, int out_size) {
    const int*   X      = (const int*)d_in[0];
    const float* hidden = (const float*)d_in[1];
    const float* emb    = (const float*)d_in[2];
    const float* W0     = (const float*)d_in[3];
    const float* Ws     = (const float*)d_in[4];
    const float* W_out  = (const float*)d_in[5];
    const float* b_out  = (const float*)d_in[6];
    (void)in_sizes; (void)n_in;

    darts_mma_kernel<<<NCTA, NTHR>>>(X, hidden, emb, W0, Ws, W_out, b_out,
                                     (float*)d_out, out_size);
}